// round 1
// baseline (speedup 1.0000x reference)
#include <cuda_runtime.h>

#define LOG2E 1.44269504088896f

// Problem dims (fixed): B=2, S=2048, D=1024, H=16, KV=4, QKB=16, VB=32
// MROWS = B*S = 4096

// -------- scratch (device globals; no allocation allowed) --------
__device__ float g_pq[4096 * 256];   // 2*log2e * sigmoid(q), [row][h*16+j]
__device__ float g_pk[4096 * 64];    // sigmoid(k), [row][kv*16+j]
__device__ float g_pv[4096 * 128];   // sigmoid(v), [row][kv*32+j]
__device__ float g_sk[4096 * 4];     // log2e * sum_j pk, [row][kv]
__device__ float g_vh[4096 * 512];   // attention output, [row][h*32+j]
__device__ float g_wo2[512 * 1024];  // (e1-e0)[i] * Wo[i][j]
__device__ float g_cvec[1024];       // sum_i e0[i] * Wo[i][j]

// -------- fast exp2 (pure FMA/ALU, no MUFU) --------
// valid for y in ~[-126, 126]; here y in [-24, 47]. rel err ~2e-6.
__device__ __forceinline__ float fast_exp2(float y) {
    float z = y + 12582912.0f;          // 1.5 * 2^23: round-to-nearest integer
    int   iz = __float_as_int(z);
    float n = z - 12582912.0f;
    float f = y - n;                    // f in [-0.5, 0.5]
    float p =            1.33335581e-3f;
    p = fmaf(p, f, 9.61812910e-3f);
    p = fmaf(p, f, 5.55041086e-2f);
    p = fmaf(p, f, 2.40226507e-1f);
    p = fmaf(p, f, 6.93147181e-1f);
    p = fmaf(p, f, 1.0f);
    float s = __int_as_float((int)(((unsigned)(iz + 127)) << 23));  // 2^n
    return s * p;
}

// -------- prep: Wo' and cvec --------
__global__ void prep_wo_kernel(const float* __restrict__ Wo,
                               const float* __restrict__ e0,
                               const float* __restrict__ e1) {
    int i = blockIdx.x * 256 + threadIdx.x;     // 512*1024 elements
    int r = i >> 10;
    g_wo2[i] = (e1[r] - e0[r]) * Wo[i];
}

__global__ void prep_cvec_kernel(const float* __restrict__ Wo,
                                 const float* __restrict__ e0) {
    int j = blockIdx.x * 256 + threadIdx.x;     // 1024 columns
    float acc = 0.f;
    #pragma unroll 8
    for (int i = 0; i < 512; i++) acc = fmaf(e0[i], Wo[i * 1024 + j], acc);
    g_cvec[j] = acc;
}

// -------- fused QKV projection GEMM + sigmoid epilogue --------
// grid.x dispatch: bx 0..3 -> Wq (N=256), bx 4 -> Wk (N=64), bx 5..6 -> Wv (N=128)
// BM=128, BN=64, BK=16, 256 threads, 8x4 micro-tile.
__global__ void __launch_bounds__(256) gemm_qkv_kernel(
    const float* __restrict__ A,
    const float* __restrict__ Wq, const float* __restrict__ Wk,
    const float* __restrict__ Wv)
{
    __shared__ __align__(16) float As[16][128];
    __shared__ __align__(16) float Bs[16][64];

    const float* Bp; float* Cp; int N, bn; float osc;
    int bx = blockIdx.x;
    if (bx < 4)       { Bp = Wq; Cp = g_pq; N = 256; bn = bx * 64;       osc = 2.0f * LOG2E; }
    else if (bx == 4) { Bp = Wk; Cp = g_pk; N = 64;  bn = 0;             osc = 1.0f; }
    else              { Bp = Wv; Cp = g_pv; N = 128; bn = (bx - 5) * 64; osc = 1.0f; }

    const int K = 1024;
    int tid  = threadIdx.x;
    int bm   = blockIdx.y * 128;
    int tx   = tid & 15, ty = tid >> 4;
    int arow = tid >> 2, acol = (tid & 3) << 2;
    int brow = tid >> 4, bcol = (tid & 15) << 2;

    float acc[8][4] = {};
    for (int k0 = 0; k0 < K; k0 += 16) {
        float4 a0 = *(const float4*)&A[(bm + arow) * K + k0 + acol];
        float4 a1 = *(const float4*)&A[(bm + arow + 64) * K + k0 + acol];
        float4 b0 = *(const float4*)&Bp[(k0 + brow) * N + bn + bcol];
        __syncthreads();
        As[acol + 0][arow] = a0.x; As[acol + 1][arow] = a0.y;
        As[acol + 2][arow] = a0.z; As[acol + 3][arow] = a0.w;
        As[acol + 0][arow + 64] = a1.x; As[acol + 1][arow + 64] = a1.y;
        As[acol + 2][arow + 64] = a1.z; As[acol + 3][arow + 64] = a1.w;
        *(float4*)&Bs[brow][bcol] = b0;
        __syncthreads();
        #pragma unroll
        for (int kk = 0; kk < 16; kk++) {
            float4 av0 = *(const float4*)&As[kk][ty * 8];
            float4 av1 = *(const float4*)&As[kk][ty * 8 + 4];
            float4 bv  = *(const float4*)&Bs[kk][tx * 4];
            float a[8] = {av0.x, av0.y, av0.z, av0.w, av1.x, av1.y, av1.z, av1.w};
            float b[4] = {bv.x, bv.y, bv.z, bv.w};
            #pragma unroll
            for (int i = 0; i < 8; i++)
                #pragma unroll
                for (int j = 0; j < 4; j++)
                    acc[i][j] = fmaf(a[i], b[j], acc[i][j]);
        }
    }
    #pragma unroll
    for (int i = 0; i < 8; i++) {
        float4 o;
        o.x = osc / (1.0f + __expf(-acc[i][0]));
        o.y = osc / (1.0f + __expf(-acc[i][1]));
        o.z = osc / (1.0f + __expf(-acc[i][2]));
        o.w = osc / (1.0f + __expf(-acc[i][3]));
        *(float4*)&Cp[(bm + ty * 8 + i) * N + bn + tx * 4] = o;
    }
}

// -------- per-key scaled sums of pk --------
__global__ void sumk_kernel() {
    int i = blockIdx.x * 256 + threadIdx.x;     // 4096*4
    int s = i >> 2, kvh = i & 3;
    const float* p = &g_pk[s * 64 + kvh * 16];
    float acc = 0.f;
    #pragma unroll
    for (int j = 0; j < 16; j++) acc += p[j];
    g_sk[i] = acc * LOG2E;
}

// -------- attention: causal single-pass softmax (no running max needed) --------
// grid: (32 row-blocks of 64, 32 = B*H). 256 threads.
// thread t: row-pair p = t/8 (rows 2p, 2p+1 of block), key lane g = t%8 (keys strided by 8).
__global__ void __launch_bounds__(256) attn_kernel() {
    __shared__ __align__(16) float s_pk[64][20];  // padded: rows hit distinct banks
    __shared__ __align__(16) float s_pv[64][36];
    __shared__ float s_sk[64];

    int bh  = blockIdx.y;
    int b   = bh >> 4, h = bh & 15;
    int kvh = h >> 2;
    int rblk = blockIdx.x;
    int tid = threadIdx.x;
    int pr  = tid >> 3, g = tid & 7;
    int r0  = rblk * 64 + pr * 2;       // global row within sequence
    int s0  = b * 2048 + r0;            // global row within [4096]

    float q0[16], q1[16];
    const float* qp = &g_pq[s0 * 256 + h * 16];
    #pragma unroll
    for (int j = 0; j < 16; j++) { q0[j] = qp[j]; q1[j] = qp[256 + j]; }

    float vh0[32], vh1[32];
    #pragma unroll
    for (int j = 0; j < 32; j++) { vh0[j] = 0.f; vh1[j] = 0.f; }
    float den0 = 0.f, den1 = 0.f;

    for (int t = 0; t <= rblk; t++) {
        int k0 = t * 64;
        __syncthreads();
        {   // cooperative tile load
            int key = tid >> 2, j4 = (tid & 3) << 2;
            *(float4*)&s_pk[key][j4] =
                *(const float4*)&g_pk[(b * 2048 + k0 + key) * 64 + kvh * 16 + j4];
            #pragma unroll
            for (int p2 = 0; p2 < 2; p2++) {
                int idx = tid + p2 * 256;
                int vk = idx >> 3, vj = (idx & 7) << 2;
                *(float4*)&s_pv[vk][vj] =
                    *(const float4*)&g_pv[(b * 2048 + k0 + vk) * 128 + kvh * 32 + vj];
            }
            if (tid < 64) s_sk[tid] = g_sk[(b * 2048 + k0 + tid) * 4 + kvh];
        }
        __syncthreads();

        for (int kk = g; kk < 64; kk += 8) {
            int kt = k0 + kk;
            const float4* kp = (const float4*)&s_pk[kk][0];
            float4 ka = kp[0], kb = kp[1], kc = kp[2], kd = kp[3];
            float kf[16] = {ka.x, ka.y, ka.z, ka.w, kb.x, kb.y, kb.z, kb.w,
                            kc.x, kc.y, kc.z, kc.w, kd.x, kd.y, kd.z, kd.w};
            float nsk = s_sk[kk];
            float y0 = -nsk, y1 = -nsk;
            #pragma unroll
            for (int j = 0; j < 16; j++) {
                y0 = fmaf(q0[j], kf[j], y0);
                y1 = fmaf(q1[j], kf[j], y1);
            }
            float e0 = (kt <= r0)     ? fast_exp2(y0) : 0.f;
            float e1 = (kt <= r0 + 1) ? fast_exp2(y1) : 0.f;
            den0 += e0; den1 += e1;
            const float4* vp = (const float4*)&s_pv[kk][0];
            #pragma unroll
            for (int j = 0; j < 8; j++) {
                float4 vv = vp[j];
                vh0[j*4+0] = fmaf(e0, vv.x, vh0[j*4+0]);
                vh0[j*4+1] = fmaf(e0, vv.y, vh0[j*4+1]);
                vh0[j*4+2] = fmaf(e0, vv.z, vh0[j*4+2]);
                vh0[j*4+3] = fmaf(e0, vv.w, vh0[j*4+3]);
                vh1[j*4+0] = fmaf(e1, vv.x, vh1[j*4+0]);
                vh1[j*4+1] = fmaf(e1, vv.y, vh1[j*4+1]);
                vh1[j*4+2] = fmaf(e1, vv.z, vh1[j*4+2]);
                vh1[j*4+3] = fmaf(e1, vv.w, vh1[j*4+3]);
            }
        }
    }

    // reduce across the 8 key-lanes of each row-pair (contiguous lanes -> xor shuffles)
    #pragma unroll
    for (int off = 4; off > 0; off >>= 1) {
        den0 += __shfl_xor_sync(0xffffffffu, den0, off);
        den1 += __shfl_xor_sync(0xffffffffu, den1, off);
        #pragma unroll
        for (int j = 0; j < 32; j++) {
            vh0[j] += __shfl_xor_sync(0xffffffffu, vh0[j], off);
            vh1[j] += __shfl_xor_sync(0xffffffffu, vh1[j], off);
        }
    }
    if (g == 0) {
        float i0 = 1.0f / den0, i1 = 1.0f / den1;
        float* o0 = &g_vh[s0 * 512 + h * 32];
        #pragma unroll
        for (int j = 0; j < 8; j++) {
            float4 w0, w1;
            w0.x = vh0[4*j+0] * i0; w0.y = vh0[4*j+1] * i0;
            w0.z = vh0[4*j+2] * i0; w0.w = vh0[4*j+3] * i0;
            w1.x = vh1[4*j+0] * i1; w1.y = vh1[4*j+1] * i1;
            w1.z = vh1[4*j+2] * i1; w1.w = vh1[4*j+3] * i1;
            *(float4*)&o0[j * 4]       = w0;
            *(float4*)&o0[512 + j * 4] = w1;
        }
    }
}

// -------- output projection: g_vh [4096,512] @ g_wo2 [512,1024] + cvec --------
__global__ void __launch_bounds__(256) gemm_out_kernel(float* __restrict__ C) {
    __shared__ __align__(16) float As[16][128];
    __shared__ __align__(16) float Bs[16][64];
    const int K = 512, N = 1024;
    const float* A = g_vh;
    const float* Bp = g_wo2;
    int bn = blockIdx.x * 64;
    int tid  = threadIdx.x;
    int bm   = blockIdx.y * 128;
    int tx   = tid & 15, ty = tid >> 4;
    int arow = tid >> 2, acol = (tid & 3) << 2;
    int brow = tid >> 4, bcol = (tid & 15) << 2;

    float acc[8][4] = {};
    for (int k0 = 0; k0 < K; k0 += 16) {
        float4 a0 = *(const float4*)&A[(bm + arow) * K + k0 + acol];
        float4 a1 = *(const float4*)&A[(bm + arow + 64) * K + k0 + acol];
        float4 b0 = *(const float4*)&Bp[(k0 + brow) * N + bn + bcol];
        __syncthreads();
        As[acol + 0][arow] = a0.x; As[acol + 1][arow] = a0.y;
        As[acol + 2][arow] = a0.z; As[acol + 3][arow] = a0.w;
        As[acol + 0][arow + 64] = a1.x; As[acol + 1][arow + 64] = a1.y;
        As[acol + 2][arow + 64] = a1.z; As[acol + 3][arow + 64] = a1.w;
        *(float4*)&Bs[brow][bcol] = b0;
        __syncthreads();
        #pragma unroll
        for (int kk = 0; kk < 16; kk++) {
            float4 av0 = *(const float4*)&As[kk][ty * 8];
            float4 av1 = *(const float4*)&As[kk][ty * 8 + 4];
            float4 bv  = *(const float4*)&Bs[kk][tx * 4];
            float a[8] = {av0.x, av0.y, av0.z, av0.w, av1.x, av1.y, av1.z, av1.w};
            float b[4] = {bv.x, bv.y, bv.z, bv.w};
            #pragma unroll
            for (int i = 0; i < 8; i++)
                #pragma unroll
                for (int j = 0; j < 4; j++)
                    acc[i][j] = fmaf(a[i], b[j], acc[i][j]);
        }
    }
    float4 cv = *(const float4*)&g_cvec[bn + tx * 4];
    #pragma unroll
    for (int i = 0; i < 8; i++) {
        float4 o;
        o.x = acc[i][0] + cv.x;
        o.y = acc[i][1] + cv.y;
        o.z = acc[i][2] + cv.z;
        o.w = acc[i][3] + cv.w;
        *(float4*)&C[(bm + ty * 8 + i) * N + bn + tx * 4] = o;
    }
}

extern "C" void kernel_launch(void* const* d_in, const int* in_sizes, int n_in,
                              void* d_out, int out_size) {
    (void)in_sizes; (void)n_in; (void)out_size;
    const float* hs = (const float*)d_in[0];
    const float* Wq = (const float*)d_in[1];
    const float* Wk = (const float*)d_in[2];
    const float* Wv = (const float*)d_in[3];
    const float* Wo = (const float*)d_in[4];
    const float* e0 = (const float*)d_in[5];
    const float* e1 = (const float*)d_in[6];
    float* out = (float*)d_out;

    prep_wo_kernel<<<2048, 256>>>(Wo, e0, e1);
    prep_cvec_kernel<<<4, 256>>>(Wo, e0);
    gemm_qkv_kernel<<<dim3(7, 32), 256>>>(hs, Wq, Wk, Wv);
    sumk_kernel<<<64, 256>>>();
    attn_kernel<<<dim3(32, 32), 256>>>();
    gemm_out_kernel<<<dim3(16, 32), 256>>>(out);
}

// round 2
// speedup vs baseline: 1.1432x; 1.1432x over previous
#include <cuda_runtime.h>

#define LOG2E 1.44269504088896f

// Dims: B=2, S=2048, D=1024, H=16, KV=4, QKB=16, VB=32. Rows M = 4096.

// -------- scratch --------
__device__ float g_pq[4096 * 256];    // 2*log2e * sigmoid(q)
__device__ float g_pk[4096 * 64];     // sigmoid(k)
__device__ float g_pv[4096 * 128];    // sigmoid(v)
__device__ float g_vh[4096 * 512];    // attention output
__device__ float g_wcat[1024 * 512];  // [Wq | Wk | Wv | 0] packed, K-major
__device__ float g_wo2[512 * 1024];   // (e1-e0)[i] * Wo[i][j]
__device__ float g_cpart[16 * 1024];  // cvec partials
__device__ float g_cvec[1024];        // sum_i e0[i]*Wo[i][j]

// -------- fast exp2, pure FMA/ALU (y in [-24, 47]) --------
__device__ __forceinline__ float fast_exp2(float y) {
    float z = y + 12582912.0f;
    int   iz = __float_as_int(z);
    float n = z - 12582912.0f;
    float f = y - n;
    float p =            1.33335581e-3f;
    p = fmaf(p, f, 9.61812910e-3f);
    p = fmaf(p, f, 5.55041086e-2f);
    p = fmaf(p, f, 2.40226507e-1f);
    p = fmaf(p, f, 6.93147181e-1f);
    p = fmaf(p, f, 1.0f);
    float s = __int_as_float((int)(((unsigned)(iz + 127)) << 23));
    return s * p;
}

__device__ __forceinline__ float sigmoidf_(float x) {
    return 1.0f / (1.0f + __expf(-x));
}

// -------- prep kernels --------
__global__ void prep_wcat_kernel(const float* __restrict__ Wq,
                                 const float* __restrict__ Wk,
                                 const float* __restrict__ Wv) {
    int idx = blockIdx.x * 256 + threadIdx.x;   // 1024*512
    int r = idx >> 9, c = idx & 511;
    float v;
    if      (c < 256) v = Wq[r * 256 + c];
    else if (c < 320) v = Wk[r * 64  + (c - 256)];
    else if (c < 448) v = Wv[r * 128 + (c - 320)];
    else              v = 0.0f;
    g_wcat[idx] = v;
}

__global__ void prep_wo_kernel(const float* __restrict__ Wo,
                               const float* __restrict__ e0,
                               const float* __restrict__ e1) {
    int i = blockIdx.x * 256 + threadIdx.x;     // 512*1024
    int r = i >> 10;
    g_wo2[i] = (e1[r] - e0[r]) * Wo[i];
}

__global__ void prep_cvec1_kernel(const float* __restrict__ Wo,
                                  const float* __restrict__ e0) {
    int ic = blockIdx.x >> 2;                   // 16 i-chunks of 32
    int j  = (blockIdx.x & 3) * 256 + threadIdx.x;
    float acc = 0.f;
    #pragma unroll
    for (int u = 0; u < 32; u++) {
        int i = ic * 32 + u;
        acc = fmaf(e0[i], Wo[i * 1024 + j], acc);
    }
    g_cpart[ic * 1024 + j] = acc;
}

__global__ void prep_cvec2_kernel() {
    int j = blockIdx.x * 256 + threadIdx.x;
    float acc = 0.f;
    #pragma unroll
    for (int ic = 0; ic < 16; ic++) acc += g_cpart[ic * 1024 + j];
    g_cvec[j] = acc;
}

// -------- QKV GEMM: hs[4096,1024] @ wcat[1024,512] -> sigmoid -> pq/pk/pv --------
// BM=64, BN=128, BK=16, 128 threads, 8x8 micro, double-buffered smem.
__global__ void __launch_bounds__(128, 3) gemm_qkv_kernel(const float* __restrict__ A) {
    __shared__ float As[2][16][68];
    __shared__ float Bs[2][16][128];
    const int K = 1024, NT = K / 16;

    int tid = threadIdx.x;
    int bm = blockIdx.y * 64;
    int bn = blockIdx.x * 128;
    int tx = tid & 15, ty = tid >> 4;

    int arow = tid >> 1, ac8 = (tid & 1) * 8;
    int brow = tid >> 5;                 // 0..3 (+4*i)
    int bcol = (tid & 31) * 4;

    float ar[8], br[16];
    const float* abase = &A[(bm + arow) * K + ac8];

    // prefetch tile 0
    *(float4*)&ar[0] = *(const float4*)(abase);
    *(float4*)&ar[4] = *(const float4*)(abase + 4);
    #pragma unroll
    for (int i = 0; i < 4; i++)
        *(float4*)&br[i * 4] = *(const float4*)&g_wcat[(brow + i * 4) * 512 + bn + bcol];
    // store tile 0
    #pragma unroll
    for (int u = 0; u < 8; u++) As[0][ac8 + u][arow] = ar[u];
    #pragma unroll
    for (int i = 0; i < 4; i++) *(float4*)&Bs[0][brow + i * 4][bcol] = *(float4*)&br[i * 4];
    __syncthreads();

    float acc[8][8];
    #pragma unroll
    for (int i = 0; i < 8; i++)
        #pragma unroll
        for (int j = 0; j < 8; j++) acc[i][j] = 0.f;

    for (int t = 0; t < NT; t++) {
        int cur = t & 1;
        if (t + 1 < NT) {
            int k0 = (t + 1) * 16;
            *(float4*)&ar[0] = *(const float4*)(abase + k0);
            *(float4*)&ar[4] = *(const float4*)(abase + k0 + 4);
            #pragma unroll
            for (int i = 0; i < 4; i++)
                *(float4*)&br[i * 4] = *(const float4*)&g_wcat[(k0 + brow + i * 4) * 512 + bn + bcol];
        }
        #pragma unroll
        for (int kk = 0; kk < 16; kk++) {
            float a[8], b[8];
            *(float4*)&a[0] = *(const float4*)&As[cur][kk][ty * 8];
            *(float4*)&a[4] = *(const float4*)&As[cur][kk][ty * 8 + 4];
            *(float4*)&b[0] = *(const float4*)&Bs[cur][kk][tx * 8];
            *(float4*)&b[4] = *(const float4*)&Bs[cur][kk][tx * 8 + 4];
            #pragma unroll
            for (int i = 0; i < 8; i++)
                #pragma unroll
                for (int j = 0; j < 8; j++)
                    acc[i][j] = fmaf(a[i], b[j], acc[i][j]);
        }
        if (t + 1 < NT) {
            int nxt = cur ^ 1;
            #pragma unroll
            for (int u = 0; u < 8; u++) As[nxt][ac8 + u][arow] = ar[u];
            #pragma unroll
            for (int i = 0; i < 4; i++) *(float4*)&Bs[nxt][brow + i * 4][bcol] = *(float4*)&br[i * 4];
        }
        __syncthreads();
    }

    // epilogue: sigmoid + scatter (8-col chunk lies in one segment; boundaries 8-aligned)
    int c0 = bn + tx * 8;
    float* base; int stride, cloc; float osc;
    if      (c0 < 256) { base = g_pq; stride = 256; cloc = c0;       osc = 2.0f * LOG2E; }
    else if (c0 < 320) { base = g_pk; stride = 64;  cloc = c0 - 256; osc = 1.0f; }
    else if (c0 < 448) { base = g_pv; stride = 128; cloc = c0 - 320; osc = 1.0f; }
    else return;
    #pragma unroll
    for (int i = 0; i < 8; i++) {
        int row = bm + ty * 8 + i;
        float4 o1, o2;
        o1.x = osc * sigmoidf_(acc[i][0]); o1.y = osc * sigmoidf_(acc[i][1]);
        o1.z = osc * sigmoidf_(acc[i][2]); o1.w = osc * sigmoidf_(acc[i][3]);
        o2.x = osc * sigmoidf_(acc[i][4]); o2.y = osc * sigmoidf_(acc[i][5]);
        o2.z = osc * sigmoidf_(acc[i][6]); o2.w = osc * sigmoidf_(acc[i][7]);
        *(float4*)&base[row * stride + cloc]     = o1;
        *(float4*)&base[row * stride + cloc + 4] = o2;
    }
}

// -------- attention --------
// 128 threads, CTA = 64 rows x 1 head. Thread = 4 rows x 8-key lane group.
// Lanes partition V columns (4 each); e broadcast via shuffle. Only diagonal tile masked.
__global__ void __launch_bounds__(128, 3) attn_kernel() {
    __shared__ float s_pk[64][20];
    __shared__ float s_pv[64][36];
    __shared__ float s_sk[64];

    int bh = blockIdx.y;
    int b = bh >> 4, h = bh & 15, kvh = h >> 2;
    int blk = blockIdx.x;
    int tid = threadIdx.x;
    int pr = tid >> 3, g = tid & 7;
    int lane = tid & 31;
    int lbase = lane & 24;
    int row0 = blk * 64 + pr * 4;
    int s0 = b * 2048 + row0;

    float q[4][16];
    #pragma unroll
    for (int i = 0; i < 4; i++) {
        const float* qp = &g_pq[(s0 + i) * 256 + h * 16];
        *(float4*)&q[i][0]  = *(const float4*)(qp);
        *(float4*)&q[i][4]  = *(const float4*)(qp + 4);
        *(float4*)&q[i][8]  = *(const float4*)(qp + 8);
        *(float4*)&q[i][12] = *(const float4*)(qp + 12);
    }

    float vh[4][4];
    #pragma unroll
    for (int i = 0; i < 4; i++)
        #pragma unroll
        for (int c = 0; c < 4; c++) vh[i][c] = 0.f;
    float den[4] = {0.f, 0.f, 0.f, 0.f};

    const float* gpk = &g_pk[(b * 2048) * 64 + kvh * 16];
    const float* gpv = &g_pv[(b * 2048) * 128 + kvh * 32];

    auto group_body = [&](int grp, bool maskd) {
        int key = grp * 8 + g;
        float kf[16];
        *(float4*)&kf[0]  = *(const float4*)&s_pk[key][0];
        *(float4*)&kf[4]  = *(const float4*)&s_pk[key][4];
        *(float4*)&kf[8]  = *(const float4*)&s_pk[key][8];
        *(float4*)&kf[12] = *(const float4*)&s_pk[key][12];
        float nsk = s_sk[key];
        float y[4];
        #pragma unroll
        for (int i = 0; i < 4; i++) y[i] = -nsk;
        #pragma unroll
        for (int j = 0; j < 16; j++)
            #pragma unroll
            for (int i = 0; i < 4; i++)
                y[i] = fmaf(q[i][j], kf[j], y[i]);
        float e[4];
        #pragma unroll
        for (int i = 0; i < 4; i++) {
            bool ok = !maskd || (key <= pr * 4 + i);
            e[i] = ok ? fast_exp2(y[i]) : 0.f;
            den[i] += e[i];
        }
        #pragma unroll
        for (int j = 0; j < 8; j++) {
            float4 vv = *(const float4*)&s_pv[grp * 8 + j][g * 4];
            float e0 = __shfl_sync(0xffffffffu, e[0], lbase | j);
            float e1 = __shfl_sync(0xffffffffu, e[1], lbase | j);
            float e2 = __shfl_sync(0xffffffffu, e[2], lbase | j);
            float e3 = __shfl_sync(0xffffffffu, e[3], lbase | j);
            vh[0][0] = fmaf(e0, vv.x, vh[0][0]); vh[0][1] = fmaf(e0, vv.y, vh[0][1]);
            vh[0][2] = fmaf(e0, vv.z, vh[0][2]); vh[0][3] = fmaf(e0, vv.w, vh[0][3]);
            vh[1][0] = fmaf(e1, vv.x, vh[1][0]); vh[1][1] = fmaf(e1, vv.y, vh[1][1]);
            vh[1][2] = fmaf(e1, vv.z, vh[1][2]); vh[1][3] = fmaf(e1, vv.w, vh[1][3]);
            vh[2][0] = fmaf(e2, vv.x, vh[2][0]); vh[2][1] = fmaf(e2, vv.y, vh[2][1]);
            vh[2][2] = fmaf(e2, vv.z, vh[2][2]); vh[2][3] = fmaf(e2, vv.w, vh[2][3]);
            vh[3][0] = fmaf(e3, vv.x, vh[3][0]); vh[3][1] = fmaf(e3, vv.y, vh[3][1]);
            vh[3][2] = fmaf(e3, vv.z, vh[3][2]); vh[3][3] = fmaf(e3, vv.w, vh[3][3]);
        }
    };

    for (int t = 0; t <= blk; t++) {
        __syncthreads();
        {
            int r = tid >> 1, c8 = (tid & 1) * 8;
            const float* src = &gpk[(t * 64 + r) * 64 + c8];
            float4 p0 = *(const float4*)src, p1 = *(const float4*)(src + 4);
            *(float4*)&s_pk[r][c8]     = p0;
            *(float4*)&s_pk[r][c8 + 4] = p1;
            float psum = p0.x + p0.y + p0.z + p0.w + p1.x + p1.y + p1.z + p1.w;
            psum += __shfl_xor_sync(0xffffffffu, psum, 1);
            if (!(tid & 1)) s_sk[r] = psum * LOG2E;
            const float* vsrc = &gpv[(t * 64 + r) * 128 + (tid & 1) * 16];
            #pragma unroll
            for (int u = 0; u < 4; u++)
                *(float4*)&s_pv[r][(tid & 1) * 16 + u * 4] = *(const float4*)(vsrc + u * 4);
        }
        __syncthreads();

        if (t < blk) {
            #pragma unroll 1
            for (int grp = 0; grp < 8; grp++) group_body(grp, false);
        } else {
            #pragma unroll 1
            for (int grp = 0; grp < 8; grp++) group_body(grp, true);
        }
    }

    // den reduction across the 8 lanes of the row-group
    #pragma unroll
    for (int off = 1; off <= 4; off <<= 1)
        #pragma unroll
        for (int i = 0; i < 4; i++)
            den[i] += __shfl_xor_sync(0xffffffffu, den[i], off);

    #pragma unroll
    for (int i = 0; i < 4; i++) {
        float inv = 1.0f / den[i];
        float4 o = make_float4(vh[i][0] * inv, vh[i][1] * inv,
                               vh[i][2] * inv, vh[i][3] * inv);
        *(float4*)&g_vh[(s0 + i) * 512 + h * 32 + g * 4] = o;
    }
}

// -------- out GEMM: g_vh[4096,512] @ g_wo2[512,1024] + cvec --------
// BM=128, BN=128, BK=16, 256 threads, 8x8 micro, double-buffered.
__global__ void __launch_bounds__(256, 2) gemm_out_kernel(float* __restrict__ C) {
    __shared__ float As[2][16][132];
    __shared__ float Bs[2][16][128];
    const int K = 512, NT = K / 16;

    int tid = threadIdx.x;
    int bm = blockIdx.y * 128;
    int bn = blockIdx.x * 128;
    int tx = tid & 15, ty = tid >> 4;

    int arow = tid >> 1, ac8 = (tid & 1) * 8;
    int brow = tid >> 5;                 // 0..7 (+8)
    int bcol = (tid & 31) * 4;

    float ar[8], br[8];
    const float* abase = &g_vh[(bm + arow) * K + ac8];

    *(float4*)&ar[0] = *(const float4*)(abase);
    *(float4*)&ar[4] = *(const float4*)(abase + 4);
    #pragma unroll
    for (int i = 0; i < 2; i++)
        *(float4*)&br[i * 4] = *(const float4*)&g_wo2[(brow + i * 8) * 1024 + bn + bcol];
    #pragma unroll
    for (int u = 0; u < 8; u++) As[0][ac8 + u][arow] = ar[u];
    #pragma unroll
    for (int i = 0; i < 2; i++) *(float4*)&Bs[0][brow + i * 8][bcol] = *(float4*)&br[i * 4];
    __syncthreads();

    float acc[8][8];
    #pragma unroll
    for (int i = 0; i < 8; i++)
        #pragma unroll
        for (int j = 0; j < 8; j++) acc[i][j] = 0.f;

    for (int t = 0; t < NT; t++) {
        int cur = t & 1;
        if (t + 1 < NT) {
            int k0 = (t + 1) * 16;
            *(float4*)&ar[0] = *(const float4*)(abase + k0);
            *(float4*)&ar[4] = *(const float4*)(abase + k0 + 4);
            #pragma unroll
            for (int i = 0; i < 2; i++)
                *(float4*)&br[i * 4] = *(const float4*)&g_wo2[(k0 + brow + i * 8) * 1024 + bn + bcol];
        }
        #pragma unroll
        for (int kk = 0; kk < 16; kk++) {
            float a[8], b[8];
            *(float4*)&a[0] = *(const float4*)&As[cur][kk][ty * 8];
            *(float4*)&a[4] = *(const float4*)&As[cur][kk][ty * 8 + 4];
            *(float4*)&b[0] = *(const float4*)&Bs[cur][kk][tx * 8];
            *(float4*)&b[4] = *(const float4*)&Bs[cur][kk][tx * 8 + 4];
            #pragma unroll
            for (int i = 0; i < 8; i++)
                #pragma unroll
                for (int j = 0; j < 8; j++)
                    acc[i][j] = fmaf(a[i], b[j], acc[i][j]);
        }
        if (t + 1 < NT) {
            int nxt = cur ^ 1;
            #pragma unroll
            for (int u = 0; u < 8; u++) As[nxt][ac8 + u][arow] = ar[u];
            #pragma unroll
            for (int i = 0; i < 2; i++) *(float4*)&Bs[nxt][brow + i * 8][bcol] = *(float4*)&br[i * 4];
        }
        __syncthreads();
    }

    float4 cva = *(const float4*)&g_cvec[bn + tx * 8];
    float4 cvb = *(const float4*)&g_cvec[bn + tx * 8 + 4];
    #pragma unroll
    for (int i = 0; i < 8; i++) {
        int row = bm + ty * 8 + i;
        float4 o1 = make_float4(acc[i][0] + cva.x, acc[i][1] + cva.y,
                                acc[i][2] + cva.z, acc[i][3] + cva.w);
        float4 o2 = make_float4(acc[i][4] + cvb.x, acc[i][5] + cvb.y,
                                acc[i][6] + cvb.z, acc[i][7] + cvb.w);
        *(float4*)&C[row * 1024 + bn + tx * 8]     = o1;
        *(float4*)&C[row * 1024 + bn + tx * 8 + 4] = o2;
    }
}

extern "C" void kernel_launch(void* const* d_in, const int* in_sizes, int n_in,
                              void* d_out, int out_size) {
    (void)in_sizes; (void)n_in; (void)out_size;
    const float* hs = (const float*)d_in[0];
    const float* Wq = (const float*)d_in[1];
    const float* Wk = (const float*)d_in[2];
    const float* Wv = (const float*)d_in[3];
    const float* Wo = (const float*)d_in[4];
    const float* e0 = (const float*)d_in[5];
    const float* e1 = (const float*)d_in[6];
    float* out = (float*)d_out;

    prep_wcat_kernel<<<2048, 256>>>(Wq, Wk, Wv);
    prep_wo_kernel<<<2048, 256>>>(Wo, e0, e1);
    prep_cvec1_kernel<<<64, 256>>>(Wo, e0);
    prep_cvec2_kernel<<<4, 256>>>();
    gemm_qkv_kernel<<<dim3(4, 64), 128>>>(hs);
    attn_kernel<<<dim3(32, 32), 128>>>();
    gemm_out_kernel<<<dim3(8, 32), 256>>>(out);
}